// round 2
// baseline (speedup 1.0000x reference)
#include <cuda_runtime.h>

// Comparator4Bit: A,B are [N,4] float32 with exact {0,1} entries (MSB first).
// Outputs: a_gt_b [N], a_eq_b [N], concatenated into d_out (2N floats).
// Since entries are exactly 0/1, pack to a 4-bit int and compare — identical
// result to the reference boolean-arithmetic formulas.

__global__ __launch_bounds__(256) void cmp4_kernel(
    const float4* __restrict__ A,   // N rows, one float4 per row
    const float4* __restrict__ B,
    float4* __restrict__ gt_out,    // N/4 float4
    float4* __restrict__ eq_out,    // N/4 float4
    int n_quads)                    // N/4
{
    int q = blockIdx.x * blockDim.x + threadIdx.x;
    if (q >= n_quads) return;

    float gt[4], eq[4];
    #pragma unroll
    for (int r = 0; r < 4; r++) {
        float4 a = __ldg(&A[q * 4 + r]);
        float4 b = __ldg(&B[q * 4 + r]);
        // Pack MSB-first bits into an int. Values are exactly 0.0f or 1.0f,
        // so float arithmetic here is exact.
        int av = ((int)a.x << 3) | ((int)a.y << 2) | ((int)a.z << 1) | (int)a.w;
        int bv = ((int)b.x << 3) | ((int)b.y << 2) | ((int)b.z << 1) | (int)b.w;
        gt[r] = (av > bv)  ? 1.0f : 0.0f;
        eq[r] = (av == bv) ? 1.0f : 0.0f;
    }
    gt_out[q] = make_float4(gt[0], gt[1], gt[2], gt[3]);
    eq_out[q] = make_float4(eq[0], eq[1], eq[2], eq[3]);
}

extern "C" void kernel_launch(void* const* d_in, const int* in_sizes, int n_in,
                              void* d_out, int out_size)
{
    const float4* A = (const float4*)d_in[0];
    const float4* B = (const float4*)d_in[1];
    int n_rows = in_sizes[0] / 4;          // N
    int n_quads = n_rows / 4;              // N divisible by 4 (N = 2^23)

    float* out = (float*)d_out;
    float4* gt_out = (float4*)out;                 // first N floats
    float4* eq_out = (float4*)(out + n_rows);      // next N floats

    int threads = 256;
    int blocks = (n_quads + threads - 1) / threads;
    cmp4_kernel<<<blocks, threads>>>(A, B, gt_out, eq_out, n_quads);
}